// round 2
// baseline (speedup 1.0000x reference)
#include <cuda_runtime.h>
#include <math.h>

#define BB   8192
#define DIN  2048
#define HH0  1024
#define HH1  512
#define LATD 128
#define NC   8

// ---------------- scratch (device globals; no runtime allocation) -----------
__device__ float g_h0[BB * HH0];   // enc0 output
__device__ float g_h1[BB * HH1];   // enc1 output
__device__ float g_z [BB * LATD];  // reparameterized latent
__device__ float g_d1[BB * HH1];   // dec0 output
__device__ float g_d0[BB * HH0];   // dec1 output
__device__ int   g_idx[BB];        // rows sorted by cluster
__device__ int   g_cnt[NC];
__device__ int   g_off[NC + 1];
__device__ int   g_cur[NC];

// ---------------- cluster counting sort --------------------------------------
__global__ void k_zero() {
    int t = threadIdx.x;
    if (t < NC) { g_cnt[t] = 0; g_cur[t] = 0; }
}

__global__ void k_hist(const int* __restrict__ lab) {
    int b = blockIdx.x * blockDim.x + threadIdx.x;
    if (b < BB) atomicAdd(&g_cnt[lab[b]], 1);
}

__global__ void k_off() {
    int s = 0;
    g_off[0] = 0;
    for (int c = 0; c < NC; c++) { s += g_cnt[c]; g_off[c + 1] = s; }
}

__global__ void k_scatter(const int* __restrict__ lab) {
    int b = blockIdx.x * blockDim.x + threadIdx.x;
    if (b < BB) {
        int c = lab[b];
        int p = atomicAdd(&g_cur[c], 1);
        g_idx[g_off[c] + p] = b;
    }
}

// ---------------- generic 128x128x16 fp32 GEMM -------------------------------
// C[m,n] = (relu?)(sum_k A[m,k] * W[k,n] + bias[n])
// GROUPED: blockIdx.z = cluster; rows gathered/scattered via g_idx,
//          W/bias offset by cluster.
template <bool GROUPED, bool RELU>
__global__ __launch_bounds__(256, 2)
void k_gemm(const float* __restrict__ A, const float* __restrict__ W,
            const float* __restrict__ bias, float* __restrict__ Cout,
            int N, int K)
{
    __shared__ float As[2][16][132];   // [k][m], padded stride keeps 16B align
    __shared__ float Bs[2][16][128];   // [k][n]

    const int tid = threadIdx.x;
    const int tx = tid & 15;          // 0..15 -> 8 output cols each
    const int ty = tid >> 4;          // 0..15 -> 8 output rows each
    const int nt = blockIdx.x, mt = blockIdx.y;

    int row_base, row_count;
    if (GROUPED) {
        int c = blockIdx.z;
        int beg = g_off[c], end = g_off[c + 1];
        row_base = beg + mt * 128;
        if (row_base >= end) return;
        row_count = min(128, end - row_base);
        W    += (size_t)c * (size_t)K * (size_t)N;
        bias += (size_t)c * (size_t)N;
    } else {
        row_base  = mt * 128;
        row_count = 128;
    }

    // A-tile load map: 512 float4 per tile, 2 per thread
    const int a_r0 = tid >> 2;                 // 0..63
    const int a_r1 = a_r0 + 64;                // 64..127
    const int a_k  = (tid & 3) * 4;            // 0,4,8,12
    // B-tile load map
    const int b_k0 = tid >> 5;                 // 0..7
    const int b_k1 = b_k0 + 8;                 // 8..15
    const int b_c  = (tid & 31) * 4;           // 0..124

    bool v0 = true, v1 = true;
    size_t gA0 = 0, gA1 = 0;
    if (GROUPED) {
        v0 = a_r0 < row_count;
        v1 = a_r1 < row_count;
        if (v0) gA0 = (size_t)g_idx[row_base + a_r0] * (size_t)K;
        if (v1) gA1 = (size_t)g_idx[row_base + a_r1] * (size_t)K;
    } else {
        gA0 = (size_t)(row_base + a_r0) * (size_t)K;
        gA1 = (size_t)(row_base + a_r1) * (size_t)K;
    }
    const float* Wn = W + (size_t)nt * 128 + b_c;

    float acc[8][8];
    #pragma unroll
    for (int i = 0; i < 8; i++)
        #pragma unroll
        for (int j = 0; j < 8; j++) acc[i][j] = 0.f;

    const int KT = K >> 4;

    // prologue: tile 0
    {
        float4 a0 = v0 ? *(const float4*)(A + gA0 + a_k) : make_float4(0.f, 0.f, 0.f, 0.f);
        float4 a1 = v1 ? *(const float4*)(A + gA1 + a_k) : make_float4(0.f, 0.f, 0.f, 0.f);
        float4 w0 = *(const float4*)(Wn + (size_t)b_k0 * N);
        float4 w1 = *(const float4*)(Wn + (size_t)b_k1 * N);
        As[0][a_k + 0][a_r0] = a0.x; As[0][a_k + 1][a_r0] = a0.y;
        As[0][a_k + 2][a_r0] = a0.z; As[0][a_k + 3][a_r0] = a0.w;
        As[0][a_k + 0][a_r1] = a1.x; As[0][a_k + 1][a_r1] = a1.y;
        As[0][a_k + 2][a_r1] = a1.z; As[0][a_k + 3][a_r1] = a1.w;
        *(float4*)&Bs[0][b_k0][b_c] = w0;
        *(float4*)&Bs[0][b_k1][b_c] = w1;
    }
    __syncthreads();

    for (int kt = 0; kt < KT; ++kt) {
        const int buf = kt & 1;
        if (kt + 1 < KT) {
            const int k0 = (kt + 1) << 4;
            float4 a0 = v0 ? *(const float4*)(A + gA0 + k0 + a_k) : make_float4(0.f, 0.f, 0.f, 0.f);
            float4 a1 = v1 ? *(const float4*)(A + gA1 + k0 + a_k) : make_float4(0.f, 0.f, 0.f, 0.f);
            float4 w0 = *(const float4*)(Wn + (size_t)(k0 + b_k0) * N);
            float4 w1 = *(const float4*)(Wn + (size_t)(k0 + b_k1) * N);
            const int nb = buf ^ 1;
            As[nb][a_k + 0][a_r0] = a0.x; As[nb][a_k + 1][a_r0] = a0.y;
            As[nb][a_k + 2][a_r0] = a0.z; As[nb][a_k + 3][a_r0] = a0.w;
            As[nb][a_k + 0][a_r1] = a1.x; As[nb][a_k + 1][a_r1] = a1.y;
            As[nb][a_k + 2][a_r1] = a1.z; As[nb][a_k + 3][a_r1] = a1.w;
            *(float4*)&Bs[nb][b_k0][b_c] = w0;
            *(float4*)&Bs[nb][b_k1][b_c] = w1;
        }
        #pragma unroll
        for (int kk = 0; kk < 16; ++kk) {
            float4 A0 = *(const float4*)&As[buf][kk][ty * 8];
            float4 A1 = *(const float4*)&As[buf][kk][ty * 8 + 4];
            float4 B0 = *(const float4*)&Bs[buf][kk][tx * 8];
            float4 B1 = *(const float4*)&Bs[buf][kk][tx * 8 + 4];
            float ar[8] = {A0.x, A0.y, A0.z, A0.w, A1.x, A1.y, A1.z, A1.w};
            float br[8] = {B0.x, B0.y, B0.z, B0.w, B1.x, B1.y, B1.z, B1.w};
            #pragma unroll
            for (int i = 0; i < 8; i++)
                #pragma unroll
                for (int j = 0; j < 8; j++)
                    acc[i][j] = fmaf(ar[i], br[j], acc[i][j]);
        }
        __syncthreads();
    }

    // epilogue
    const float* bp = bias + (size_t)nt * 128 + tx * 8;
    float bv[8];
    #pragma unroll
    for (int j = 0; j < 8; j++) bv[j] = bp[j];

    #pragma unroll
    for (int i = 0; i < 8; i++) {
        const int lr = ty * 8 + i;
        if (GROUPED && lr >= row_count) continue;
        size_t gr = GROUPED ? (size_t)g_idx[row_base + lr] : (size_t)(row_base + lr);
        float* cp = Cout + gr * (size_t)N + (size_t)nt * 128 + tx * 8;
        float o[8];
        #pragma unroll
        for (int j = 0; j < 8; j++) {
            float v = acc[i][j] + bv[j];
            if (RELU) v = fmaxf(v, 0.f);
            o[j] = v;
        }
        *(float4*)(cp + 0) = make_float4(o[0], o[1], o[2], o[3]);
        *(float4*)(cp + 4) = make_float4(o[4], o[5], o[6], o[7]);
    }
}

// ---------------- reparameterize ---------------------------------------------
__global__ void k_reparam(const float* __restrict__ mu, const float* __restrict__ lv,
                          const float* __restrict__ eps, float* __restrict__ z, int n)
{
    int i = blockIdx.x * blockDim.x + threadIdx.x;
    if (i < n) z[i] = mu[i] + eps[i] * expf(0.5f * lv[i]);
}

// ---------------- launch ------------------------------------------------------
extern "C" void kernel_launch(void* const* d_in, const int* in_sizes, int n_in,
                              void* d_out, int out_size)
{
    const float* x      = (const float*)d_in[0];
    const int*   lab    = (const int*)d_in[1];
    const float* eps    = (const float*)d_in[2];
    const float* W_enc0 = (const float*)d_in[3];
    const float* b_enc0 = (const float*)d_in[4];
    const float* W_enc1 = (const float*)d_in[5];
    const float* b_enc1 = (const float*)d_in[6];
    const float* W_mu   = (const float*)d_in[7];
    const float* b_mu   = (const float*)d_in[8];
    const float* W_lv   = (const float*)d_in[9];
    const float* b_lv   = (const float*)d_in[10];
    const float* W_dec0 = (const float*)d_in[11];
    const float* b_dec0 = (const float*)d_in[12];
    const float* W_dec1 = (const float*)d_in[13];
    const float* b_dec1 = (const float*)d_in[14];
    const float* W_out  = (const float*)d_in[15];
    const float* b_out  = (const float*)d_in[16];

    float* recon = (float*)d_out;
    float* mu    = recon + (size_t)BB * DIN;
    float* lv    = mu + (size_t)BB * LATD;

    float *h0, *h1, *z, *d1, *d0;
    cudaGetSymbolAddress((void**)&h0, g_h0);
    cudaGetSymbolAddress((void**)&h1, g_h1);
    cudaGetSymbolAddress((void**)&z,  g_z);
    cudaGetSymbolAddress((void**)&d1, g_d1);
    cudaGetSymbolAddress((void**)&d0, g_d0);

    // cluster counting sort
    k_zero<<<1, 32>>>();
    k_hist<<<BB / 256, 256>>>(lab);
    k_off<<<1, 1>>>();
    k_scatter<<<BB / 256, 256>>>(lab);

    // encoder
    k_gemm<true,  true ><<<dim3(HH0 / 128, BB / 128, NC), 256>>>(x,  W_enc0, b_enc0, h0, HH0, DIN);
    k_gemm<false, true ><<<dim3(HH1 / 128, BB / 128),     256>>>(h0, W_enc1, b_enc1, h1, HH1, HH0);
    // latent heads
    k_gemm<false, false><<<dim3(1, BB / 128),             256>>>(h1, W_mu, b_mu, mu, LATD, HH1);
    k_gemm<false, false><<<dim3(1, BB / 128),             256>>>(h1, W_lv, b_lv, lv, LATD, HH1);
    k_reparam<<<(BB * LATD) / 256, 256>>>(mu, lv, eps, z, BB * LATD);
    // decoder
    k_gemm<false, true ><<<dim3(HH1 / 128, BB / 128),     256>>>(z,  W_dec0, b_dec0, d1, HH1, LATD);
    k_gemm<true,  true ><<<dim3(HH0 / 128, BB / 128, NC), 256>>>(d1, W_dec1, b_dec1, d0, HH0, HH1);
    k_gemm<false, false><<<dim3(DIN / 128, BB / 128),     256>>>(d0, W_out, b_out, recon, DIN, HH0);
}

// round 4
// speedup vs baseline: 2.1505x; 2.1505x over previous
#include <cuda_runtime.h>
#include <cuda_bf16.h>
#include <math.h>
#include <stdint.h>

#define BB   8192
#define DIN  2048
#define HH0  1024
#define HH1  512
#define LATD 128
#define NC   8

// ---------------- scratch (device globals) -----------------------------------
__device__ __nv_bfloat16 g_xs_hi[BB*DIN], g_xs_lo[BB*DIN];
__device__ __nv_bfloat16 g_h0_hi[BB*HH0], g_h0_lo[BB*HH0];
__device__ __nv_bfloat16 g_h1_hi[BB*HH1], g_h1_lo[BB*HH1];
__device__ __nv_bfloat16 g_z_hi [BB*LATD], g_z_lo [BB*LATD];
__device__ __nv_bfloat16 g_d1_hi[BB*HH1], g_d1_lo[BB*HH1];
__device__ __nv_bfloat16 g_d0_hi[BB*HH0], g_d0_lo[BB*HH0];
__device__ float g_mu_s[BB*LATD], g_lv_s[BB*LATD];

// transposed weight planes [N,K] (bf16 hi/lo)
__device__ __nv_bfloat16 g_wenc0_hi[NC*DIN*HH0], g_wenc0_lo[NC*DIN*HH0];
__device__ __nv_bfloat16 g_wenc1_hi[HH0*HH1],    g_wenc1_lo[HH0*HH1];
__device__ __nv_bfloat16 g_wmu_hi [HH1*LATD],    g_wmu_lo [HH1*LATD];
__device__ __nv_bfloat16 g_wlv_hi [HH1*LATD],    g_wlv_lo [HH1*LATD];
__device__ __nv_bfloat16 g_wdec0_hi[LATD*HH1],   g_wdec0_lo[LATD*HH1];
__device__ __nv_bfloat16 g_wdec1_hi[NC*HH1*HH0], g_wdec1_lo[NC*HH1*HH0];
__device__ __nv_bfloat16 g_wout_hi[HH0*DIN],     g_wout_lo[HH0*DIN];

__device__ int g_idx[BB], g_cnt[NC], g_off[NC+1], g_cur[NC];

// ---------------- PTX helpers -------------------------------------------------
__device__ __forceinline__ uint32_t smem_u32(const void* p) {
    uint32_t a;
    asm("{ .reg .u64 t; cvta.to.shared.u64 t, %1; cvt.u32.u64 %0, t; }" : "=r"(a) : "l"(p));
    return a;
}
__device__ __forceinline__ void cp16(uint32_t saddr, const void* g) {
    asm volatile("cp.async.cg.shared.global [%0], [%1], 16;" :: "r"(saddr), "l"(g));
}
#define CP_COMMIT() asm volatile("cp.async.commit_group;" ::: "memory")
#define CP_WAIT(n)  asm volatile("cp.async.wait_group %0;" :: "n"(n) : "memory")

__device__ __forceinline__ void ldsm4(uint32_t* r, uint32_t addr) {
    asm volatile("ldmatrix.sync.aligned.m8n8.x4.shared.b16 {%0,%1,%2,%3}, [%4];"
        : "=r"(r[0]), "=r"(r[1]), "=r"(r[2]), "=r"(r[3]) : "r"(addr));
}
__device__ __forceinline__ void mma16816(float* c, const uint32_t* a, const uint32_t* b) {
    asm volatile("mma.sync.aligned.m16n8k16.row.col.f32.bf16.bf16.f32 "
        "{%0,%1,%2,%3}, {%4,%5,%6,%7}, {%8,%9}, {%0,%1,%2,%3};"
        : "+f"(c[0]), "+f"(c[1]), "+f"(c[2]), "+f"(c[3])
        : "r"(a[0]), "r"(a[1]), "r"(a[2]), "r"(a[3]), "r"(b[0]), "r"(b[1]));
}

// smem layout: rows of 64B (32 bf16), chunk swizzle c' = c ^ ((row>>1)&3)
__device__ __forceinline__ uint32_t swz(int row, int c) {
    return (uint32_t)(row * 64 + ((c ^ ((row >> 1) & 3)) << 4));
}

// ---------------- cluster counting sort ---------------------------------------
__global__ void k_zero() { int t = threadIdx.x; if (t < NC) { g_cnt[t] = 0; g_cur[t] = 0; } }
__global__ void k_hist(const int* __restrict__ lab) {
    int b = blockIdx.x * blockDim.x + threadIdx.x;
    if (b < BB) atomicAdd(&g_cnt[lab[b]], 1);
}
__global__ void k_off() {
    int s = 0; g_off[0] = 0;
    for (int c = 0; c < NC; c++) { s += g_cnt[c]; g_off[c+1] = s; }
}
__global__ void k_scatter(const int* __restrict__ lab) {
    int b = blockIdx.x * blockDim.x + threadIdx.x;
    if (b < BB) { int c = lab[b]; int p = atomicAdd(&g_cur[c], 1); g_idx[g_off[c] + p] = b; }
}

// ---------------- permute + split-convert x -----------------------------------
__global__ void k_permx(const float* __restrict__ x) {
    int p = blockIdx.x;
    int orig = g_idx[p];
    const float* src = x + (size_t)orig * DIN;
    __nv_bfloat16* dh = g_xs_hi + (size_t)p * DIN;
    __nv_bfloat16* dl = g_xs_lo + (size_t)p * DIN;
    for (int i = threadIdx.x; i < DIN; i += 256) {
        float v = src[i];
        __nv_bfloat16 h = __float2bfloat16_rn(v);
        dh[i] = h;
        dl[i] = __float2bfloat16_rn(v - __bfloat162float(h));
    }
}

// ---------------- weight transpose + split-convert: W[K,N] -> T[N,K] ----------
__global__ void k_convw(const float* __restrict__ W, __nv_bfloat16* __restrict__ Th,
                        __nv_bfloat16* __restrict__ Tl, int K, int N) {
    __shared__ float tile[32][33];
    int c = blockIdx.z;
    size_t mo = (size_t)c * K * N;
    W += mo; Th += mo; Tl += mo;
    int n0 = blockIdx.x * 32, k0 = blockIdx.y * 32;
    int tx = threadIdx.x, ty = threadIdx.y;
    #pragma unroll
    for (int i = ty; i < 32; i += 8)
        tile[i][tx] = W[(size_t)(k0 + i) * N + n0 + tx];
    __syncthreads();
    #pragma unroll
    for (int i = ty; i < 32; i += 8) {
        float v = tile[tx][i];   // = W[k0+tx][n0+i]
        __nv_bfloat16 h = __float2bfloat16_rn(v);
        size_t o = (size_t)(n0 + i) * K + k0 + tx;
        Th[o] = h;
        Tl[o] = __float2bfloat16_rn(v - __bfloat162float(h));
    }
}

// ---------------- warp-MMA split-bf16 GEMM ------------------------------------
// CTA tile 128x128, K-stage 32, 3-stage cp.async pipeline.
// Warp tile m64 x n32 (8 warps: 2 in M, 4 in N).
#define PLANE   8192              // 128 rows * 64B
#define STAGEB  (4 * PLANE)       // Ahi, Alo, Bhi, Blo
#define NSTAGE  3
#define SMEMB   (NSTAGE * STAGEB) // 96KB

template<bool GROUPED, bool RELU, int OUT_MODE>  // 0=bf16 planes sorted, 1=fp32 sorted, 2=fp32 scatter
__global__ __launch_bounds__(256, 1)
void k_gemm_mma(const __nv_bfloat16* __restrict__ Ahi, const __nv_bfloat16* __restrict__ Alo,
                const __nv_bfloat16* __restrict__ Whi, const __nv_bfloat16* __restrict__ Wlo,
                const float* __restrict__ bias,
                void* __restrict__ outA, void* __restrict__ outB,
                int Ktot, int Ntot)
{
    extern __shared__ char smem[];
    const int t = threadIdx.x;
    const int lane = t & 31, wid = t >> 5;
    const int wm = wid & 1, wn = wid >> 1;
    const int nt = blockIdx.x, mt = blockIdx.y;

    int row_base, row_hi;
    if (GROUPED) {
        int c = blockIdx.z;
        int beg = g_off[c], end = g_off[c + 1];
        row_base = beg + mt * 128;
        if (row_base >= end) return;
        row_hi = end - 1;
        size_t wo = (size_t)c * Ktot * Ntot;
        Whi += wo; Wlo += wo; bias += (size_t)c * Ntot;
    } else {
        row_base = mt * 128;
        row_hi = BB - 1;
    }

    const uint32_t sb = smem_u32(smem);

    // ---- loader maps: each thread loads 2x16B per plane per stage ----
    const int lrow = t >> 1;                 // 0..127
    const int lc0  = (t & 1) * 2;            // chunk pair {0,1} or {2,3}
    int arow = row_base + lrow;
    if (GROUPED) arow = min(arow, row_hi);
    const char* gAh = (const char*)(Ahi + (size_t)arow * Ktot) + lc0 * 16;
    const char* gAl = (const char*)(Alo + (size_t)arow * Ktot) + lc0 * 16;
    const int brow = nt * 128 + lrow;
    const char* gBh = (const char*)(Whi + (size_t)brow * Ktot) + lc0 * 16;
    const char* gBl = (const char*)(Wlo + (size_t)brow * Ktot) + lc0 * 16;
    const uint32_t so0 = swz(lrow, lc0);
    const uint32_t so1 = swz(lrow, lc0 + 1);

#define ISSUE(S_) do { \
    uint32_t base_ = sb + ((S_) % NSTAGE) * STAGEB; \
    size_t gk_ = (size_t)(S_) * 64; \
    cp16(base_ + 0*PLANE + so0, gAh + gk_); cp16(base_ + 0*PLANE + so1, gAh + gk_ + 16); \
    cp16(base_ + 1*PLANE + so0, gAl + gk_); cp16(base_ + 1*PLANE + so1, gAl + gk_ + 16); \
    cp16(base_ + 2*PLANE + so0, gBh + gk_); cp16(base_ + 2*PLANE + so1, gBh + gk_ + 16); \
    cp16(base_ + 3*PLANE + so0, gBl + gk_); cp16(base_ + 3*PLANE + so1, gBl + gk_ + 16); \
    } while (0)

    // ---- fragment read offsets (ks toggles bit 5) ----
    uint32_t a_rd[4], b_rd[2];
    {
        const int ar = wm * 64 + (lane & 15);
        #pragma unroll
        for (int mi = 0; mi < 4; mi++) a_rd[mi] = swz(ar + mi * 16, (lane >> 4));
        const int br = wn * 32 + (lane & 7) + ((lane >> 4) & 1) * 8;
        #pragma unroll
        for (int nip = 0; nip < 2; nip++) b_rd[nip] = swz(br + nip * 16, (lane >> 3) & 1);
    }

    float acc[4][4][4];
    #pragma unroll
    for (int mi = 0; mi < 4; mi++)
        #pragma unroll
        for (int ni = 0; ni < 4; ni++)
            #pragma unroll
            for (int q = 0; q < 4; q++) acc[mi][ni][q] = 0.f;

    const int S = Ktot >> 5;

    // prologue
    ISSUE(0); CP_COMMIT();
    ISSUE(1); CP_COMMIT();

    for (int s = 0; s < S; s++) {
        CP_WAIT(NSTAGE - 2);
        __syncthreads();
        if (s + NSTAGE - 1 < S) ISSUE(s + NSTAGE - 1);
        CP_COMMIT();

        const uint32_t base = sb + (s % NSTAGE) * STAGEB;
        #pragma unroll
        for (int ks = 0; ks < 2; ks++) {
            const uint32_t kx = (uint32_t)ks << 5;
            uint32_t aH[4][4], aL[4][4], bH[2][4], bL[2][4];
            #pragma unroll
            for (int mi = 0; mi < 4; mi++) {
                ldsm4(aH[mi], base + 0*PLANE + (a_rd[mi] ^ kx));
                ldsm4(aL[mi], base + 1*PLANE + (a_rd[mi] ^ kx));
            }
            #pragma unroll
            for (int nip = 0; nip < 2; nip++) {
                ldsm4(bH[nip], base + 2*PLANE + (b_rd[nip] ^ kx));
                ldsm4(bL[nip], base + 3*PLANE + (b_rd[nip] ^ kx));
            }
            #pragma unroll
            for (int mi = 0; mi < 4; mi++) {
                #pragma unroll
                for (int ni = 0; ni < 4; ni++) {
                    const uint32_t* bh = &bH[ni >> 1][(ni & 1) * 2];
                    const uint32_t* bl = &bL[ni >> 1][(ni & 1) * 2];
                    mma16816(acc[mi][ni], aH[mi], bh);
                    mma16816(acc[mi][ni], aH[mi], bl);
                    mma16816(acc[mi][ni], aL[mi], bh);
                }
            }
        }
        __syncthreads();
    }
#undef ISSUE

    // ---------------- epilogue ----------------
    const int colq = (lane & 3) * 2;           // col pair within n8
    float2 bv[4];
    #pragma unroll
    for (int ni = 0; ni < 4; ni++) {
        int col = nt * 128 + wn * 32 + ni * 8 + colq;
        bv[ni] = *(const float2*)(bias + col);
    }

    #pragma unroll
    for (int mi = 0; mi < 4; mi++) {
        #pragma unroll
        for (int rr = 0; rr < 2; rr++) {
            const int row_local = wm * 64 + mi * 16 + rr * 8 + (lane >> 2);
            const int row_global = row_base + row_local;
            if (GROUPED && row_global > row_hi) continue;
            #pragma unroll
            for (int ni = 0; ni < 4; ni++) {
                const int col = nt * 128 + wn * 32 + ni * 8 + colq;
                float v0 = acc[mi][ni][rr * 2 + 0] + bv[ni].x;
                float v1 = acc[mi][ni][rr * 2 + 1] + bv[ni].y;
                if (RELU) { v0 = fmaxf(v0, 0.f); v1 = fmaxf(v1, 0.f); }
                if (OUT_MODE == 0) {
                    __nv_bfloat16 h0 = __float2bfloat16_rn(v0);
                    __nv_bfloat16 h1 = __float2bfloat16_rn(v1);
                    __nv_bfloat16 l0 = __float2bfloat16_rn(v0 - __bfloat162float(h0));
                    __nv_bfloat16 l1 = __float2bfloat16_rn(v1 - __bfloat162float(h1));
                    uint32_t ph = ((uint32_t)__bfloat16_as_ushort(h1) << 16) | __bfloat16_as_ushort(h0);
                    uint32_t pl = ((uint32_t)__bfloat16_as_ushort(l1) << 16) | __bfloat16_as_ushort(l0);
                    *(uint32_t*)((__nv_bfloat16*)outA + (size_t)row_global * Ntot + col) = ph;
                    *(uint32_t*)((__nv_bfloat16*)outB + (size_t)row_global * Ntot + col) = pl;
                } else {
                    size_t orow = (OUT_MODE == 2) ? (size_t)g_idx[row_global] : (size_t)row_global;
                    *(float2*)((float*)outA + orow * Ntot + col) = make_float2(v0, v1);
                }
            }
        }
    }
}

// ---------------- reparameterize + scatter mu/logvar --------------------------
__global__ void k_reparam(const float* __restrict__ eps, float* __restrict__ out_mu,
                          float* __restrict__ out_lv) {
    int i = blockIdx.x * blockDim.x + threadIdx.x;
    if (i >= BB * LATD) return;
    int p = i >> 7, l = i & 127;
    int orig = g_idx[p];
    float m = g_mu_s[i], lvv = g_lv_s[i];
    float z = m + eps[(size_t)orig * LATD + l] * expf(0.5f * lvv);
    __nv_bfloat16 h = __float2bfloat16_rn(z);
    g_z_hi[i] = h;
    g_z_lo[i] = __float2bfloat16_rn(z - __bfloat162float(h));
    out_mu[(size_t)orig * LATD + l] = m;
    out_lv[(size_t)orig * LATD + l] = lvv;
}

// ---------------- launch -------------------------------------------------------
extern "C" void kernel_launch(void* const* d_in, const int* in_sizes, int n_in,
                              void* d_out, int out_size)
{
    const float* x      = (const float*)d_in[0];
    const int*   lab    = (const int*)d_in[1];
    const float* eps    = (const float*)d_in[2];
    const float* W_enc0 = (const float*)d_in[3];
    const float* b_enc0 = (const float*)d_in[4];
    const float* W_enc1 = (const float*)d_in[5];
    const float* b_enc1 = (const float*)d_in[6];
    const float* W_mu   = (const float*)d_in[7];
    const float* b_mu   = (const float*)d_in[8];
    const float* W_lv   = (const float*)d_in[9];
    const float* b_lv   = (const float*)d_in[10];
    const float* W_dec0 = (const float*)d_in[11];
    const float* b_dec0 = (const float*)d_in[12];
    const float* W_dec1 = (const float*)d_in[13];
    const float* b_dec1 = (const float*)d_in[14];
    const float* W_out  = (const float*)d_in[15];
    const float* b_out  = (const float*)d_in[16];

    float* recon = (float*)d_out;
    float* mu    = recon + (size_t)BB * DIN;
    float* lv    = mu + (size_t)BB * LATD;

    void *xs_h, *xs_l, *h0_h, *h0_l, *h1_h, *h1_l, *z_h, *z_l, *d1_h, *d1_l, *d0_h, *d0_l;
    void *mu_s, *lv_s;
    void *we0h, *we0l, *we1h, *we1l, *wmh, *wml, *wlh, *wll, *wd0h, *wd0l, *wd1h, *wd1l, *woh, *wol;
    cudaGetSymbolAddress(&xs_h, g_xs_hi); cudaGetSymbolAddress(&xs_l, g_xs_lo);
    cudaGetSymbolAddress(&h0_h, g_h0_hi); cudaGetSymbolAddress(&h0_l, g_h0_lo);
    cudaGetSymbolAddress(&h1_h, g_h1_hi); cudaGetSymbolAddress(&h1_l, g_h1_lo);
    cudaGetSymbolAddress(&z_h,  g_z_hi);  cudaGetSymbolAddress(&z_l,  g_z_lo);
    cudaGetSymbolAddress(&d1_h, g_d1_hi); cudaGetSymbolAddress(&d1_l, g_d1_lo);
    cudaGetSymbolAddress(&d0_h, g_d0_hi); cudaGetSymbolAddress(&d0_l, g_d0_lo);
    cudaGetSymbolAddress(&mu_s, g_mu_s);  cudaGetSymbolAddress(&lv_s, g_lv_s);
    cudaGetSymbolAddress(&we0h, g_wenc0_hi); cudaGetSymbolAddress(&we0l, g_wenc0_lo);
    cudaGetSymbolAddress(&we1h, g_wenc1_hi); cudaGetSymbolAddress(&we1l, g_wenc1_lo);
    cudaGetSymbolAddress(&wmh,  g_wmu_hi);   cudaGetSymbolAddress(&wml,  g_wmu_lo);
    cudaGetSymbolAddress(&wlh,  g_wlv_hi);   cudaGetSymbolAddress(&wll,  g_wlv_lo);
    cudaGetSymbolAddress(&wd0h, g_wdec0_hi); cudaGetSymbolAddress(&wd0l, g_wdec0_lo);
    cudaGetSymbolAddress(&wd1h, g_wdec1_hi); cudaGetSymbolAddress(&wd1l, g_wdec1_lo);
    cudaGetSymbolAddress(&woh,  g_wout_hi);  cudaGetSymbolAddress(&wol,  g_wout_lo);

    cudaFuncSetAttribute(k_gemm_mma<true,  true,  0>, cudaFuncAttributeMaxDynamicSharedMemorySize, SMEMB);
    cudaFuncSetAttribute(k_gemm_mma<false, true,  0>, cudaFuncAttributeMaxDynamicSharedMemorySize, SMEMB);
    cudaFuncSetAttribute(k_gemm_mma<false, false, 1>, cudaFuncAttributeMaxDynamicSharedMemorySize, SMEMB);
    cudaFuncSetAttribute(k_gemm_mma<false, false, 2>, cudaFuncAttributeMaxDynamicSharedMemorySize, SMEMB);

    // sort rows by cluster
    k_zero<<<1, 32>>>();
    k_hist<<<BB / 256, 256>>>(lab);
    k_off<<<1, 1>>>();
    k_scatter<<<BB / 256, 256>>>(lab);

    // permute + convert inputs; convert weights (transpose to [N,K] planes)
    k_permx<<<BB, 256>>>(x);
    dim3 cb(32, 8);
    k_convw<<<dim3(HH0/32,  DIN/32,  NC), cb>>>(W_enc0, (__nv_bfloat16*)we0h, (__nv_bfloat16*)we0l, DIN,  HH0);
    k_convw<<<dim3(HH1/32,  HH0/32,  1),  cb>>>(W_enc1, (__nv_bfloat16*)we1h, (__nv_bfloat16*)we1l, HH0,  HH1);
    k_convw<<<dim3(LATD/32, HH1/32,  1),  cb>>>(W_mu,   (__nv_bfloat16*)wmh,  (__nv_bfloat16*)wml,  HH1,  LATD);
    k_convw<<<dim3(LATD/32, HH1/32,  1),  cb>>>(W_lv,   (__nv_bfloat16*)wlh,  (__nv_bfloat16*)wll,  HH1,  LATD);
    k_convw<<<dim3(HH1/32,  LATD/32, 1),  cb>>>(W_dec0, (__nv_bfloat16*)wd0h, (__nv_bfloat16*)wd0l, LATD, HH1);
    k_convw<<<dim3(HH0/32,  HH1/32,  NC), cb>>>(W_dec1, (__nv_bfloat16*)wd1h, (__nv_bfloat16*)wd1l, HH1,  HH0);
    k_convw<<<dim3(DIN/32,  HH0/32,  1),  cb>>>(W_out,  (__nv_bfloat16*)woh,  (__nv_bfloat16*)wol,  HH0,  DIN);

    const int MT = BB / 128;   // 64

    // encoder
    k_gemm_mma<true, true, 0><<<dim3(HH0/128, MT, NC), 256, SMEMB>>>(
        (const __nv_bfloat16*)xs_h, (const __nv_bfloat16*)xs_l,
        (const __nv_bfloat16*)we0h, (const __nv_bfloat16*)we0l, b_enc0, h0_h, h0_l, DIN, HH0);
    k_gemm_mma<false, true, 0><<<dim3(HH1/128, MT), 256, SMEMB>>>(
        (const __nv_bfloat16*)h0_h, (const __nv_bfloat16*)h0_l,
        (const __nv_bfloat16*)we1h, (const __nv_bfloat16*)we1l, b_enc1, h1_h, h1_l, HH0, HH1);
    // latent heads (fp32, sorted)
    k_gemm_mma<false, false, 1><<<dim3(1, MT), 256, SMEMB>>>(
        (const __nv_bfloat16*)h1_h, (const __nv_bfloat16*)h1_l,
        (const __nv_bfloat16*)wmh, (const __nv_bfloat16*)wml, b_mu, mu_s, nullptr, HH1, LATD);
    k_gemm_mma<false, false, 1><<<dim3(1, MT), 256, SMEMB>>>(
        (const __nv_bfloat16*)h1_h, (const __nv_bfloat16*)h1_l,
        (const __nv_bfloat16*)wlh, (const __nv_bfloat16*)wll, b_lv, lv_s, nullptr, HH1, LATD);
    k_reparam<<<(BB * LATD) / 256, 256>>>(eps, mu, lv);
    // decoder
    k_gemm_mma<false, true, 0><<<dim3(HH1/128, MT), 256, SMEMB>>>(
        (const __nv_bfloat16*)z_h, (const __nv_bfloat16*)z_l,
        (const __nv_bfloat16*)wd0h, (const __nv_bfloat16*)wd0l, b_dec0, d1_h, d1_l, LATD, HH1);
    k_gemm_mma<true, true, 0><<<dim3(HH0/128, MT, NC), 256, SMEMB>>>(
        (const __nv_bfloat16*)d1_h, (const __nv_bfloat16*)d1_l,
        (const __nv_bfloat16*)wd1h, (const __nv_bfloat16*)wd1l, b_dec1, d0_h, d0_l, HH1, HH0);
    k_gemm_mma<false, false, 2><<<dim3(DIN/128, MT), 256, SMEMB>>>(
        (const __nv_bfloat16*)d0_h, (const __nv_bfloat16*)d0_l,
        (const __nv_bfloat16*)woh, (const __nv_bfloat16*)wol, b_out, recon, nullptr, HH0, DIN);
}

// round 8
// speedup vs baseline: 2.1797x; 1.0136x over previous
#include <cuda_runtime.h>
#include <cuda_bf16.h>
#include <math.h>
#include <stdint.h>

#define BB   8192
#define DIN  2048
#define HH0  1024
#define HH1  512
#define LATD 128
#define NC   8

// ---------------- scratch (device globals) -----------------------------------
__device__ __nv_bfloat16 g_xs_hi[BB*DIN], g_xs_lo[BB*DIN];
__device__ __nv_bfloat16 g_h0_hi[BB*HH0], g_h0_lo[BB*HH0];
__device__ __nv_bfloat16 g_h1_hi[BB*HH1], g_h1_lo[BB*HH1];
__device__ __nv_bfloat16 g_z_hi [BB*LATD], g_z_lo [BB*LATD];
__device__ __nv_bfloat16 g_d1_hi[BB*HH1], g_d1_lo[BB*HH1];
__device__ __nv_bfloat16 g_d0_hi[BB*HH0], g_d0_lo[BB*HH0];
__device__ float g_mulv_s[BB * 2 * LATD];     // [row][0:128]=mu, [128:256]=logvar (sorted)
__device__ float g_bml[2 * LATD];

// transposed weight planes [N,K] (bf16 hi/lo)
__device__ __nv_bfloat16 g_wenc0_hi[NC*DIN*HH0], g_wenc0_lo[NC*DIN*HH0];
__device__ __nv_bfloat16 g_wenc1_hi[HH0*HH1],    g_wenc1_lo[HH0*HH1];
__device__ __nv_bfloat16 g_wml_hi [2*LATD*HH1],  g_wml_lo [2*LATD*HH1];   // mu cols 0-127, lv 128-255
__device__ __nv_bfloat16 g_wdec0_hi[LATD*HH1],   g_wdec0_lo[LATD*HH1];
__device__ __nv_bfloat16 g_wdec1_hi[NC*HH1*HH0], g_wdec1_lo[NC*HH1*HH0];
__device__ __nv_bfloat16 g_wout_hi[HH0*DIN],     g_wout_lo[HH0*DIN];

__device__ int g_idx[BB], g_cnt[NC], g_off[NC+1], g_cur[NC];

// ---------------- PTX helpers -------------------------------------------------
__device__ __forceinline__ uint32_t smem_u32(const void* p) {
    uint32_t a;
    asm("{ .reg .u64 t; cvta.to.shared.u64 t, %1; cvt.u32.u64 %0, t; }" : "=r"(a) : "l"(p));
    return a;
}
__device__ __forceinline__ void cp16(uint32_t saddr, const void* g) {
    asm volatile("cp.async.cg.shared.global [%0], [%1], 16;" :: "r"(saddr), "l"(g));
}
#define CP_COMMIT() asm volatile("cp.async.commit_group;" ::: "memory")
#define CP_WAIT(n)  asm volatile("cp.async.wait_group %0;" :: "n"(n) : "memory")

__device__ __forceinline__ void ldsm4(uint32_t* r, uint32_t addr) {
    asm volatile("ldmatrix.sync.aligned.m8n8.x4.shared.b16 {%0,%1,%2,%3}, [%4];"
        : "=r"(r[0]), "=r"(r[1]), "=r"(r[2]), "=r"(r[3]) : "r"(addr));
}
__device__ __forceinline__ void mma16816(float* c, const uint32_t* a, const uint32_t* b) {
    asm volatile("mma.sync.aligned.m16n8k16.row.col.f32.bf16.bf16.f32 "
        "{%0,%1,%2,%3}, {%4,%5,%6,%7}, {%8,%9}, {%0,%1,%2,%3};"
        : "+f"(c[0]), "+f"(c[1]), "+f"(c[2]), "+f"(c[3])
        : "r"(a[0]), "r"(a[1]), "r"(a[2]), "r"(a[3]), "r"(b[0]), "r"(b[1]));
}

// smem layout: rows of 64B (32 bf16), chunk swizzle c' = c ^ ((row>>1)&3)
__device__ __forceinline__ uint32_t swz(int row, int c) {
    return (uint32_t)(row * 64 + ((c ^ ((row >> 1) & 3)) << 4));
}

// ---------------- cluster counting sort ---------------------------------------
__global__ void k_zero() { int t = threadIdx.x; if (t < NC) { g_cnt[t] = 0; g_cur[t] = 0; } }
__global__ void k_hist(const int* __restrict__ lab) {
    int b = blockIdx.x * blockDim.x + threadIdx.x;
    if (b < BB) atomicAdd(&g_cnt[lab[b]], 1);
}
__global__ void k_off() {
    int s = 0; g_off[0] = 0;
    for (int c = 0; c < NC; c++) { s += g_cnt[c]; g_off[c+1] = s; }
}
__global__ void k_scatter(const int* __restrict__ lab) {
    int b = blockIdx.x * blockDim.x + threadIdx.x;
    if (b < BB) { int c = lab[b]; int p = atomicAdd(&g_cur[c], 1); g_idx[g_off[c] + p] = b; }
}

// ---------------- permute + split-convert x -----------------------------------
__global__ void k_permx(const float* __restrict__ x) {
    int p = blockIdx.x;
    int orig = g_idx[p];
    const float* src = x + (size_t)orig * DIN;
    __nv_bfloat16* dh = g_xs_hi + (size_t)p * DIN;
    __nv_bfloat16* dl = g_xs_lo + (size_t)p * DIN;
    for (int i = threadIdx.x; i < DIN; i += 256) {
        float v = src[i];
        __nv_bfloat16 h = __float2bfloat16_rn(v);
        dh[i] = h;
        dl[i] = __float2bfloat16_rn(v - __bfloat162float(h));
    }
}

// ---------------- weight transpose + split-convert: W[K,N] -> T[N,K] ----------
__global__ void k_convw(const float* __restrict__ W, __nv_bfloat16* __restrict__ Th,
                        __nv_bfloat16* __restrict__ Tl, int K, int N) {
    __shared__ float tile[32][33];
    int c = blockIdx.z;
    size_t mo = (size_t)c * K * N;
    W += mo; Th += mo; Tl += mo;
    int n0 = blockIdx.x * 32, k0 = blockIdx.y * 32;
    int tx = threadIdx.x, ty = threadIdx.y;
    #pragma unroll
    for (int i = ty; i < 32; i += 8)
        tile[i][tx] = W[(size_t)(k0 + i) * N + n0 + tx];
    __syncthreads();
    #pragma unroll
    for (int i = ty; i < 32; i += 8) {
        float v = tile[tx][i];
        __nv_bfloat16 h = __float2bfloat16_rn(v);
        size_t o = (size_t)(n0 + i) * K + k0 + tx;
        Th[o] = h;
        Tl[o] = __float2bfloat16_rn(v - __bfloat162float(h));
    }
}

__global__ void k_catbias(const float* __restrict__ bm, const float* __restrict__ blv) {
    int t = threadIdx.x;
    g_bml[t] = (t < LATD) ? bm[t] : blv[t - LATD];
}

// ---------------- warp-MMA split-bf16 GEMM ------------------------------------
// CTA tile 256x128, K-stage 32, 3-stage cp.async pipeline, 512 threads
// (16 warps: 4 in M x 4 in N, warp tile m64 x n32).
#define A_PL    16384             // 256 rows * 64B
#define B_PL    8192              // 128 rows * 64B
#define STAGEB  (2*A_PL + 2*B_PL) // 49152
#define NSTAGE  3
#define SMEMB   (NSTAGE * STAGEB) // 147456

template<bool GROUPED, bool RELU, int OUT_MODE>  // 0=bf16 planes sorted, 1=fp32 sorted, 2=fp32 scatter
__global__ __launch_bounds__(512, 1)
void k_gemm_mma(const __nv_bfloat16* __restrict__ Ahi, const __nv_bfloat16* __restrict__ Alo,
                const __nv_bfloat16* __restrict__ Whi, const __nv_bfloat16* __restrict__ Wlo,
                const float* __restrict__ bias,
                void* __restrict__ outA, void* __restrict__ outB,
                int Ktot, int Ntot)
{
    extern __shared__ char smem[];
    const int t = threadIdx.x;
    const int lane = t & 31, wid = t >> 5;
    const int wm = wid & 3, wn = wid >> 2;
    const int nt = blockIdx.x, mt = blockIdx.y;

    int row_base, row_hi;
    if (GROUPED) {
        int c = blockIdx.z;
        int beg = g_off[c], end = g_off[c + 1];
        row_base = beg + mt * 256;
        if (row_base >= end) return;
        row_hi = end - 1;
        size_t wo = (size_t)c * Ktot * Ntot;
        Whi += wo; Wlo += wo; bias += (size_t)c * Ntot;
    } else {
        row_base = mt * 256;
        row_hi = BB - 1;
    }

    const uint32_t sb = smem_u32(smem);

    // ---- loader maps ----
    // A: 2 chunks/plane/thread: row = t>>1 (0..255), chunk pair (t&1)*2
    const int lrow = t >> 1;
    const int lc0  = (t & 1) * 2;
    int arow = row_base + lrow;
    if (GROUPED) arow = min(arow, row_hi);
    const char* gAh = (const char*)(Ahi + (size_t)arow * Ktot) + lc0 * 16;
    const char* gAl = (const char*)(Alo + (size_t)arow * Ktot) + lc0 * 16;
    const uint32_t so0 = swz(lrow, lc0);
    const uint32_t so1 = swz(lrow, lc0 + 1);
    // B: 1 chunk/plane/thread: row = t>>2 (0..127), chunk t&3
    const int brow_l = t >> 2;
    const int bc = t & 3;
    const int brow = nt * 128 + brow_l;
    const char* gBh = (const char*)(Whi + (size_t)brow * Ktot) + bc * 16;
    const char* gBl = (const char*)(Wlo + (size_t)brow * Ktot) + bc * 16;
    const uint32_t sob = swz(brow_l, bc);

#define ISSUE(S_) do { \
    uint32_t base_ = sb + ((S_) % NSTAGE) * STAGEB; \
    size_t gk_ = (size_t)(S_) * 64; \
    cp16(base_ + so0,               gAh + gk_); cp16(base_ + so1,               gAh + gk_ + 16); \
    cp16(base_ + A_PL + so0,        gAl + gk_); cp16(base_ + A_PL + so1,        gAl + gk_ + 16); \
    cp16(base_ + 2*A_PL + sob,        gBh + gk_); \
    cp16(base_ + 2*A_PL + B_PL + sob, gBl + gk_); \
    } while (0)

    // ---- fragment read offsets (ks toggles bit 5) ----
    uint32_t a_rd[4], b_rd[2];
    {
        const int ar = wm * 64 + (lane & 15);
        #pragma unroll
        for (int mi = 0; mi < 4; mi++) a_rd[mi] = swz(ar + mi * 16, (lane >> 4));
        const int br = wn * 32 + (lane & 7) + ((lane >> 4) & 1) * 8;
        #pragma unroll
        for (int nip = 0; nip < 2; nip++) b_rd[nip] = swz(br + nip * 16, (lane >> 3) & 1);
    }

    float acc[4][4][4];
    #pragma unroll
    for (int mi = 0; mi < 4; mi++)
        #pragma unroll
        for (int ni = 0; ni < 4; ni++)
            #pragma unroll
            for (int q = 0; q < 4; q++) acc[mi][ni][q] = 0.f;

    const int S = Ktot >> 5;

    ISSUE(0); CP_COMMIT();
    ISSUE(1); CP_COMMIT();

    for (int s = 0; s < S; s++) {
        CP_WAIT(NSTAGE - 2);
        __syncthreads();
        if (s + NSTAGE - 1 < S) ISSUE(s + NSTAGE - 1);
        CP_COMMIT();

        const uint32_t base = sb + (s % NSTAGE) * STAGEB;
        #pragma unroll
        for (int ks = 0; ks < 2; ks++) {
            const uint32_t kx = (uint32_t)ks << 5;
            uint32_t bH[2][4], bL[2][4], af[4][4];
            #pragma unroll
            for (int nip = 0; nip < 2; nip++) {
                ldsm4(bH[nip], base + 2*A_PL + (b_rd[nip] ^ kx));
                ldsm4(bL[nip], base + 2*A_PL + B_PL + (b_rd[nip] ^ kx));
            }
            // aH pass: aH*bH + aH*bL
            #pragma unroll
            for (int mi = 0; mi < 4; mi++) ldsm4(af[mi], base + (a_rd[mi] ^ kx));
            #pragma unroll
            for (int mi = 0; mi < 4; mi++)
                #pragma unroll
                for (int ni = 0; ni < 4; ni++) {
                    mma16816(acc[mi][ni], af[mi], &bH[ni >> 1][(ni & 1) * 2]);
                    mma16816(acc[mi][ni], af[mi], &bL[ni >> 1][(ni & 1) * 2]);
                }
            // aL pass: aL*bH (overwrite af)
            #pragma unroll
            for (int mi = 0; mi < 4; mi++) ldsm4(af[mi], base + A_PL + (a_rd[mi] ^ kx));
            #pragma unroll
            for (int mi = 0; mi < 4; mi++)
                #pragma unroll
                for (int ni = 0; ni < 4; ni++)
                    mma16816(acc[mi][ni], af[mi], &bH[ni >> 1][(ni & 1) * 2]);
        }
        __syncthreads();
    }
#undef ISSUE

    // ---------------- epilogue ----------------
    const int colq = (lane & 3) * 2;
    float2 bv[4];
    #pragma unroll
    for (int ni = 0; ni < 4; ni++) {
        int col = nt * 128 + wn * 32 + ni * 8 + colq;
        bv[ni] = *(const float2*)(bias + col);
    }

    #pragma unroll
    for (int mi = 0; mi < 4; mi++) {
        #pragma unroll
        for (int rr = 0; rr < 2; rr++) {
            const int row_local = wm * 64 + mi * 16 + rr * 8 + (lane >> 2);
            const int row_global = row_base + row_local;
            if (GROUPED && row_global > row_hi) continue;
            #pragma unroll
            for (int ni = 0; ni < 4; ni++) {
                const int col = nt * 128 + wn * 32 + ni * 8 + colq;
                float v0 = acc[mi][ni][rr * 2 + 0] + bv[ni].x;
                float v1 = acc[mi][ni][rr * 2 + 1] + bv[ni].y;
                if (RELU) { v0 = fmaxf(v0, 0.f); v1 = fmaxf(v1, 0.f); }
                if (OUT_MODE == 0) {
                    __nv_bfloat16 h0 = __float2bfloat16_rn(v0);
                    __nv_bfloat16 h1 = __float2bfloat16_rn(v1);
                    __nv_bfloat16 l0 = __float2bfloat16_rn(v0 - __bfloat162float(h0));
                    __nv_bfloat16 l1 = __float2bfloat16_rn(v1 - __bfloat162float(h1));
                    uint32_t ph = ((uint32_t)__bfloat16_as_ushort(h1) << 16) | __bfloat16_as_ushort(h0);
                    uint32_t pl = ((uint32_t)__bfloat16_as_ushort(l1) << 16) | __bfloat16_as_ushort(l0);
                    *(uint32_t*)((__nv_bfloat16*)outA + (size_t)row_global * Ntot + col) = ph;
                    *(uint32_t*)((__nv_bfloat16*)outB + (size_t)row_global * Ntot + col) = pl;
                } else {
                    size_t orow = (OUT_MODE == 2) ? (size_t)g_idx[row_global] : (size_t)row_global;
                    *(float2*)((float*)outA + orow * Ntot + col) = make_float2(v0, v1);
                }
            }
        }
    }
}

// ---------------- reparameterize + scatter mu/logvar --------------------------
__global__ void k_reparam(const float* __restrict__ eps, float* __restrict__ out_mu,
                          float* __restrict__ out_lv) {
    int i = blockIdx.x * blockDim.x + threadIdx.x;
    if (i >= BB * LATD) return;
    int p = i >> 7, l = i & 127;
    int orig = g_idx[p];
    float m   = g_mulv_s[(size_t)p * 256 + l];
    float lvv = g_mulv_s[(size_t)p * 256 + 128 + l];
    float z = m + eps[(size_t)orig * LATD + l] * expf(0.5f * lvv);
    __nv_bfloat16 h = __float2bfloat16_rn(z);
    g_z_hi[i] = h;
    g_z_lo[i] = __float2bfloat16_rn(z - __bfloat162float(h));
    out_mu[(size_t)orig * LATD + l] = m;
    out_lv[(size_t)orig * LATD + l] = lvv;
}

// ---------------- launch -------------------------------------------------------
extern "C" void kernel_launch(void* const* d_in, const int* in_sizes, int n_in,
                              void* d_out, int out_size)
{
    const float* x      = (const float*)d_in[0];
    const int*   lab    = (const int*)d_in[1];
    const float* eps    = (const float*)d_in[2];
    const float* W_enc0 = (const float*)d_in[3];
    const float* b_enc0 = (const float*)d_in[4];
    const float* W_enc1 = (const float*)d_in[5];
    const float* b_enc1 = (const float*)d_in[6];
    const float* W_mu   = (const float*)d_in[7];
    const float* b_mu   = (const float*)d_in[8];
    const float* W_lv   = (const float*)d_in[9];
    const float* b_lv   = (const float*)d_in[10];
    const float* W_dec0 = (const float*)d_in[11];
    const float* b_dec0 = (const float*)d_in[12];
    const float* W_dec1 = (const float*)d_in[13];
    const float* b_dec1 = (const float*)d_in[14];
    const float* W_out  = (const float*)d_in[15];
    const float* b_out  = (const float*)d_in[16];

    float* recon = (float*)d_out;
    float* mu    = recon + (size_t)BB * DIN;
    float* lv    = mu + (size_t)BB * LATD;

    void *xs_h, *xs_l, *h0_h, *h0_l, *h1_h, *h1_l, *z_h, *z_l, *d1_h, *d1_l, *d0_h, *d0_l;
    void *mulv_s, *bml;
    void *we0h, *we0l, *we1h, *we1l, *wmlh, *wmll, *wd0h, *wd0l, *wd1h, *wd1l, *woh, *wol;
    cudaGetSymbolAddress(&xs_h, g_xs_hi); cudaGetSymbolAddress(&xs_l, g_xs_lo);
    cudaGetSymbolAddress(&h0_h, g_h0_hi); cudaGetSymbolAddress(&h0_l, g_h0_lo);
    cudaGetSymbolAddress(&h1_h, g_h1_hi); cudaGetSymbolAddress(&h1_l, g_h1_lo);
    cudaGetSymbolAddress(&z_h,  g_z_hi);  cudaGetSymbolAddress(&z_l,  g_z_lo);
    cudaGetSymbolAddress(&d1_h, g_d1_hi); cudaGetSymbolAddress(&d1_l, g_d1_lo);
    cudaGetSymbolAddress(&d0_h, g_d0_hi); cudaGetSymbolAddress(&d0_l, g_d0_lo);
    cudaGetSymbolAddress(&mulv_s, g_mulv_s); cudaGetSymbolAddress(&bml, g_bml);
    cudaGetSymbolAddress(&we0h, g_wenc0_hi); cudaGetSymbolAddress(&we0l, g_wenc0_lo);
    cudaGetSymbolAddress(&we1h, g_wenc1_hi); cudaGetSymbolAddress(&we1l, g_wenc1_lo);
    cudaGetSymbolAddress(&wmlh, g_wml_hi);   cudaGetSymbolAddress(&wmll, g_wml_lo);
    cudaGetSymbolAddress(&wd0h, g_wdec0_hi); cudaGetSymbolAddress(&wd0l, g_wdec0_lo);
    cudaGetSymbolAddress(&wd1h, g_wdec1_hi); cudaGetSymbolAddress(&wd1l, g_wdec1_lo);
    cudaGetSymbolAddress(&woh,  g_wout_hi);  cudaGetSymbolAddress(&wol,  g_wout_lo);

    cudaFuncSetAttribute(k_gemm_mma<true,  true,  0>, cudaFuncAttributeMaxDynamicSharedMemorySize, SMEMB);
    cudaFuncSetAttribute(k_gemm_mma<false, true,  0>, cudaFuncAttributeMaxDynamicSharedMemorySize, SMEMB);
    cudaFuncSetAttribute(k_gemm_mma<false, false, 1>, cudaFuncAttributeMaxDynamicSharedMemorySize, SMEMB);
    cudaFuncSetAttribute(k_gemm_mma<false, false, 2>, cudaFuncAttributeMaxDynamicSharedMemorySize, SMEMB);

    // sort rows by cluster
    k_zero<<<1, 32>>>();
    k_hist<<<BB / 256, 256>>>(lab);
    k_off<<<1, 1>>>();
    k_scatter<<<BB / 256, 256>>>(lab);

    // permute + convert inputs; convert weights (transpose to [N,K] planes)
    k_permx<<<BB, 256>>>(x);
    dim3 cb(32, 8);
    k_convw<<<dim3(HH0/32,  DIN/32,  NC), cb>>>(W_enc0, (__nv_bfloat16*)we0h, (__nv_bfloat16*)we0l, DIN,  HH0);
    k_convw<<<dim3(HH1/32,  HH0/32,  1),  cb>>>(W_enc1, (__nv_bfloat16*)we1h, (__nv_bfloat16*)we1l, HH0,  HH1);
    k_convw<<<dim3(LATD/32, HH1/32,  1),  cb>>>(W_mu, (__nv_bfloat16*)wmlh, (__nv_bfloat16*)wmll, HH1, LATD);
    k_convw<<<dim3(LATD/32, HH1/32,  1),  cb>>>(W_lv, (__nv_bfloat16*)wmlh + (size_t)LATD*HH1,
                                                     (__nv_bfloat16*)wmll + (size_t)LATD*HH1, HH1, LATD);
    k_convw<<<dim3(HH1/32,  LATD/32, 1),  cb>>>(W_dec0, (__nv_bfloat16*)wd0h, (__nv_bfloat16*)wd0l, LATD, HH1);
    k_convw<<<dim3(HH0/32,  HH1/32,  NC), cb>>>(W_dec1, (__nv_bfloat16*)wd1h, (__nv_bfloat16*)wd1l, HH1,  HH0);
    k_convw<<<dim3(DIN/32,  HH0/32,  1),  cb>>>(W_out,  (__nv_bfloat16*)woh,  (__nv_bfloat16*)wol,  HH0,  DIN);
    k_catbias<<<1, 256>>>(b_mu, b_lv);

    const int MT = BB / 256;   // 32

    // encoder
    k_gemm_mma<true, true, 0><<<dim3(HH0/128, MT, NC), 512, SMEMB>>>(
        (const __nv_bfloat16*)xs_h, (const __nv_bfloat16*)xs_l,
        (const __nv_bfloat16*)we0h, (const __nv_bfloat16*)we0l, b_enc0, h0_h, h0_l, DIN, HH0);
    k_gemm_mma<false, true, 0><<<dim3(HH1/128, MT), 512, SMEMB>>>(
        (const __nv_bfloat16*)h0_h, (const __nv_bfloat16*)h0_l,
        (const __nv_bfloat16*)we1h, (const __nv_bfloat16*)we1l, b_enc1, h1_h, h1_l, HH0, HH1);
    // fused latent heads (N=256: mu|logvar), fp32, sorted
    k_gemm_mma<false, false, 1><<<dim3(2, MT), 512, SMEMB>>>(
        (const __nv_bfloat16*)h1_h, (const __nv_bfloat16*)h1_l,
        (const __nv_bfloat16*)wmlh, (const __nv_bfloat16*)wmll, (const float*)bml,
        mulv_s, nullptr, HH1, 2 * LATD);
    k_reparam<<<(BB * LATD) / 256, 256>>>(eps, mu, lv);
    // decoder
    k_gemm_mma<false, true, 0><<<dim3(HH1/128, MT), 512, SMEMB>>>(
        (const __nv_bfloat16*)z_h, (const __nv_bfloat16*)z_l,
        (const __nv_bfloat16*)wd0h, (const __nv_bfloat16*)wd0l, b_dec0, d1_h, d1_l, LATD, HH1);
    k_gemm_mma<true, true, 0><<<dim3(HH0/128, MT, NC), 512, SMEMB>>>(
        (const __nv_bfloat16*)d1_h, (const __nv_bfloat16*)d1_l,
        (const __nv_bfloat16*)wd1h, (const __nv_bfloat16*)wd1l, b_dec1, d0_h, d0_l, HH1, HH0);
    k_gemm_mma<false, false, 2><<<dim3(DIN/128, MT), 512, SMEMB>>>(
        (const __nv_bfloat16*)d0_h, (const __nv_bfloat16*)d0_l,
        (const __nv_bfloat16*)woh, (const __nv_bfloat16*)wol, b_out, recon, nullptr, HH0, DIN);
}